// round 9
// baseline (speedup 1.0000x reference)
#include <cuda_runtime.h>
#include <cstdint>

// Lower-triangular matvec: y[i] = sum_{j<=i} W[i,j] * x[j]
// n = 8192, W row-major fp32 (lower triangle = 128 MB, streamed once).
//
// R9: pair-block (block b -> rows b, n-1-b; exactly n+1 floats/block).
// Both rows' float4 data (<= 2048 float4 = 32 KB) streamed into smem via
// cp.async in 4 chunks/commit-groups, all issued up front (in-flight bytes
// live in smem: zero register cost). Each thread copies EXACTLY the entries
// it consumes (j = 512c + tid, +256), so there are NO barriers in the main
// path; consumption rolls chunk-by-chunk with wait_group 3/2/1/0, overlapping
// compute with the remaining DRAM arrivals. ~40 regs -> 6 blocks/SM (vs R8's
// register-limited 4), eliminating the aligned copy/compute phase gaps.

#define NTHREADS 256
#define CHUNK4   512                   // float4 per chunk (8 KB)
#define BUF4     2048                  // total float4 capacity (32 KB)

__device__ __forceinline__ float dot4(float4 w, float4 v) {
    return w.x * v.x + w.y * v.y + w.z * v.z + w.w * v.w;
}

__device__ __forceinline__ void cp_async16(void* dst_smem, const void* src_gmem) {
    uint32_t d = (uint32_t)__cvta_generic_to_shared(dst_smem);
    asm volatile("cp.async.cg.shared.global [%0], [%1], 16;"
                 :: "r"(d), "l"(src_gmem) : "memory");
}
__device__ __forceinline__ void cp_commit() {
    asm volatile("cp.async.commit_group;" ::: "memory");
}
template <int N>
__device__ __forceinline__ void cp_wait() {
    asm volatile("cp.async.wait_group %0;" :: "n"(N) : "memory");
}

__global__ __launch_bounds__(NTHREADS)
void tril_mv_kernel(const float* __restrict__ x,
                    const float* __restrict__ W,
                    float* __restrict__ y,
                    int n)
{
    __shared__ __align__(16) float4 buf[BUF4];     // 32 KB
    __shared__ float red0[NTHREADS / 32];
    __shared__ float red1[NTHREADS / 32];

    const int tid = threadIdx.x;
    const int b   = blockIdx.x;
    const int r0  = b;
    const int r1  = n - 1 - b;

    const int len0 = r0 + 1;
    const int len1 = r1 + 1;
    const int m0   = len0 >> 2;                    // float4s, row 0
    const int m1   = len1 >> 2;                    // float4s, row 1
    const int tot  = m0 + m1;                      // 2047 or 2048

    const float4* __restrict__ W40 =
        reinterpret_cast<const float4*>(W + (size_t)r0 * n);
    const float4* __restrict__ W41 =
        reinterpret_cast<const float4*>(W + (size_t)r1 * n);
    const float4* __restrict__ x4 = reinterpret_cast<const float4*>(x);

    // ---- issue all 4 chunks up front (one commit group each) ----
    #pragma unroll
    for (int c = 0; c < 4; c++) {
        int j = c * CHUNK4 + tid;
        if (j < tot)
            cp_async16(&buf[j], (j < m0) ? (const void*)(W40 + j)
                                         : (const void*)(W41 + (j - m0)));
        int j2 = j + NTHREADS;
        if (j2 < tot)
            cp_async16(&buf[j2], (j2 < m0) ? (const void*)(W40 + j2)
                                           : (const void*)(W41 + (j2 - m0)));
        cp_commit();
    }

    float acc0 = 0.0f, acc1 = 0.0f;

    // ---- rolling consume: wait one group at a time, no barriers ----
    // Each thread reads back exactly the entries it copied.
    #define CONSUME(c)                                                     \
    {                                                                      \
        int j = (c) * CHUNK4 + tid;                                        \
        if (j < tot) {                                                     \
            int col = (j < m0) ? j : (j - m0);                             \
            float p = dot4(buf[j], __ldg(x4 + col));                       \
            if (j < m0) acc0 += p; else acc1 += p;                         \
        }                                                                  \
        int j2 = j + NTHREADS;                                             \
        if (j2 < tot) {                                                    \
            int col = (j2 < m0) ? j2 : (j2 - m0);                          \
            float p = dot4(buf[j2], __ldg(x4 + col));                      \
            if (j2 < m0) acc0 += p; else acc1 += p;                        \
        }                                                                  \
    }

    cp_wait<3>(); CONSUME(0);
    cp_wait<2>(); CONSUME(1);
    cp_wait<1>(); CONSUME(2);
    cp_wait<0>(); CONSUME(3);
    #undef CONSUME

    // ---- scalar tails (len % 4 floats per row, direct from gmem) ----
    {
        const int t0 = len0 & 3;
        if (tid < t0) {
            const int j = (m0 << 2) + tid;
            acc0 += W[(size_t)r0 * n + j] * x[j];
        }
        const int t1 = len1 & 3;
        if (tid < t1) {
            const int j = (m1 << 2) + tid;
            acc1 += W[(size_t)r1 * n + j] * x[j];
        }
    }

    // ---- dual block reduction ----
    #pragma unroll
    for (int off = 16; off > 0; off >>= 1) {
        acc0 += __shfl_down_sync(0xffffffffu, acc0, off);
        acc1 += __shfl_down_sync(0xffffffffu, acc1, off);
    }
    const int warp = tid >> 5;
    const int lane = tid & 31;
    if (lane == 0) { red0[warp] = acc0; red1[warp] = acc1; }
    __syncthreads();

    if (warp == 0) {
        float a0 = (lane < NTHREADS / 32) ? red0[lane] : 0.0f;
        float a1 = (lane < NTHREADS / 32) ? red1[lane] : 0.0f;
        #pragma unroll
        for (int off = (NTHREADS / 64); off > 0; off >>= 1) {
            a0 += __shfl_down_sync(0xffffffffu, a0, off);
            a1 += __shfl_down_sync(0xffffffffu, a1, off);
        }
        if (lane == 0) { y[r0] = a0; y[r1] = a1; }
    }
}

extern "C" void kernel_launch(void* const* d_in, const int* in_sizes, int n_in,
                              void* d_out, int out_size) {
    const float* x = (const float*)d_in[0];   // [n]
    const float* W = (const float*)d_in[1];   // [n, n] row-major
    float*       y = (float*)d_out;           // [n]

    const int n = in_sizes[0];                // 8192 (even)

    tril_mv_kernel<<<n / 2, NTHREADS>>>(x, W, y, n);
}

// round 10
// speedup vs baseline: 1.0270x; 1.0270x over previous
#include <cuda_runtime.h>
#include <cstdint>

// Lower-triangular matvec: y[i] = sum_{j<=i} W[i,j] * x[j]
// n = 8192, W row-major fp32 (lower triangle = 128 MB, streamed once).
//
// R10: persistent-wave ring pipeline. Grid = 888 blocks (6/SM, one resident
// wave, blocks never die mid-kernel). Block b processes pairs b, b+888, ...
// (pair p -> rows p and n-1-p, n+1 floats each: balanced). W streams through
// a 4-stage x 8KB cp.async ring; each thread copies EXACTLY the smem slots it
// later reads (self-consuming ring -> no barriers in the ring path, per-thread
// commit/wait_group FIFO). After consuming each 8KB chunk the thread
// immediately issues the replacement chunk of the NEXT pair, so DRAM request
// issue never pauses across pair boundaries -- attacking the ~40% DRAM idle
// duty cycle that every block-per-pair design showed.

#define NTHREADS 256
#define STAGE4   512      // float4 per stage (8 KB)
#define STAGES   4
#define GRID     888      // 148 SMs * 6 blocks

__device__ __forceinline__ float dot4(float4 w, float4 v) {
    return w.x * v.x + w.y * v.y + w.z * v.z + w.w * v.w;
}

__device__ __forceinline__ void cp_async16(void* dst_smem, const void* src_gmem) {
    uint32_t d = (uint32_t)__cvta_generic_to_shared(dst_smem);
    asm volatile("cp.async.cg.shared.global [%0], [%1], 16;"
                 :: "r"(d), "l"(src_gmem) : "memory");
}
__device__ __forceinline__ void cp_commit() {
    asm volatile("cp.async.commit_group;" ::: "memory");
}
template <int N>
__device__ __forceinline__ void cp_wait() {
    asm volatile("cp.async.wait_group %0;" :: "n"(N) : "memory");
}

__global__ __launch_bounds__(NTHREADS)
void tril_mv_kernel(const float* __restrict__ x,
                    const float* __restrict__ W,
                    float* __restrict__ y,
                    int n)
{
    __shared__ __align__(16) float4 ring[STAGES][STAGE4];   // 32 KB
    __shared__ float red0[NTHREADS / 32];
    __shared__ float red1[NTHREADS / 32];

    const int tid    = threadIdx.x;
    const int npairs = n >> 1;
    const float4* __restrict__ x4 = reinterpret_cast<const float4*>(x);

    // --- issue chunk c of pair p into ring stage c (one commit group) ---
    auto issue = [&](int p, int c) {
        const int m0  = (p + 1) >> 2;
        const int tot = m0 + ((n - p) >> 2);
        const float4* __restrict__ W40 =
            reinterpret_cast<const float4*>(W + (size_t)p * n);
        const float4* __restrict__ W41 =
            reinterpret_cast<const float4*>(W + (size_t)(n - 1 - p) * n);
        const int j = c * STAGE4 + tid;
        if (j < tot)
            cp_async16(&ring[c][tid],
                       (j < m0) ? (const void*)(W40 + j)
                                : (const void*)(W41 + (j - m0)));
        const int j2 = j + NTHREADS;
        if (j2 < tot)
            cp_async16(&ring[c][tid + NTHREADS],
                       (j2 < m0) ? (const void*)(W40 + j2)
                                 : (const void*)(W41 + (j2 - m0)));
        cp_commit();
    };

    int p = blockIdx.x;

    // Prologue: fill the ring with pair p's 4 chunks.
    if (p < npairs) {
        #pragma unroll
        for (int c = 0; c < STAGES; c++) issue(p, c);
    }

    while (p < npairs) {
        const int pn  = p + GRID;                 // next pair for this block
        const bool more = (pn < npairs);

        const int m0  = (p + 1) >> 2;
        const int tot = m0 + ((n - p) >> 2);

        float acc0 = 0.0f, acc1 = 0.0f;

        #pragma unroll
        for (int c = 0; c < STAGES; c++) {
            // Wait until chunk c of pair p has landed. If we keep refilling,
            // pending groups stay at 4 -> wait<3>. On the last pair the FIFO
            // drains, so the level drops with c.
            if (more) { cp_wait<3>(); }
            else {
                if      (c == 0) cp_wait<3>();
                else if (c == 1) cp_wait<2>();
                else if (c == 2) cp_wait<1>();
                else             cp_wait<0>();
            }

            const int j = c * STAGE4 + tid;
            if (j < tot) {
                const int col = (j < m0) ? j : (j - m0);
                const float v = dot4(ring[c][tid], __ldg(x4 + col));
                if (j < m0) acc0 += v; else acc1 += v;
            }
            const int j2 = j + NTHREADS;
            if (j2 < tot) {
                const int col = (j2 < m0) ? j2 : (j2 - m0);
                const float v = dot4(ring[c][tid + NTHREADS], __ldg(x4 + col));
                if (j2 < m0) acc0 += v; else acc1 += v;
            }

            // Immediately refill this stage with the next pair's chunk c:
            // load issue never pauses across pair boundaries.
            if (more) issue(pn, c);
        }

        // Scalar tails (len % 4 floats per row, direct from gmem).
        {
            const int len0 = p + 1;
            const int len1 = n - p;
            const int t0 = len0 & 3;
            if (tid < t0) {
                const int j = ((len0 >> 2) << 2) + tid;
                acc0 += W[(size_t)p * n + j] * x[j];
            }
            const int t1 = len1 & 3;
            if (tid < t1) {
                const int j = ((len1 >> 2) << 2) + tid;
                acc1 += W[(size_t)(n - 1 - p) * n + j] * x[j];
            }
        }

        // Block reduction for this pair (issues above overlap the barriers).
        #pragma unroll
        for (int off = 16; off > 0; off >>= 1) {
            acc0 += __shfl_down_sync(0xffffffffu, acc0, off);
            acc1 += __shfl_down_sync(0xffffffffu, acc1, off);
        }
        const int warp = tid >> 5;
        const int lane = tid & 31;
        if (lane == 0) { red0[warp] = acc0; red1[warp] = acc1; }
        __syncthreads();
        if (warp == 0) {
            float a0 = (lane < NTHREADS / 32) ? red0[lane] : 0.0f;
            float a1 = (lane < NTHREADS / 32) ? red1[lane] : 0.0f;
            #pragma unroll
            for (int off = (NTHREADS / 64); off > 0; off >>= 1) {
                a0 += __shfl_down_sync(0xffffffffu, a0, off);
                a1 += __shfl_down_sync(0xffffffffu, a1, off);
            }
            if (lane == 0) { y[p] = a0; y[n - 1 - p] = a1; }
        }
        __syncthreads();   // red reuse guard for next pair

        p = pn;
    }
}

extern "C" void kernel_launch(void* const* d_in, const int* in_sizes, int n_in,
                              void* d_out, int out_size) {
    const float* x = (const float*)d_in[0];   // [n]
    const float* W = (const float*)d_in[1];   // [n, n] row-major
    float*       y = (float*)d_out;           // [n]

    const int n = in_sizes[0];                // 8192 (even)

    // Ask for max shared-memory carveout so 6 blocks/SM (198 KB) fit.
    static int carveout_set = 0;
    if (!carveout_set) {
        cudaFuncSetAttribute(tril_mv_kernel,
                             cudaFuncAttributePreferredSharedMemoryCarveout, 100);
        carveout_set = 1;
    }

    tril_mv_kernel<<<GRID, NTHREADS>>>(x, W, y, n);
}